// round 1
// baseline (speedup 1.0000x reference)
#include <cuda_runtime.h>
#include <cstddef>

// Problem constants (static in reference)
constexpr int Mm = 512;      // tokens
constexpr int Nn = 4096;     // model dim
constexpr int Kdim = 4096;   // inner dim of projections
constexpr int Dd = 128;      // head dim
constexpr int Hh = 32;       // heads
constexpr int Ll = 4096;     // cache length
constexpr int Pp = 3584;     // append offset (P + M == L)
constexpr size_t OUT0 = (size_t)Mm * Nn;   // offset of perturb_out in d_out

// Scratch (device globals: allocation-free per harness rules)
__device__ float g_q[(size_t)Hh * Mm * Dd];          //  8 MB  [H][M][D]
__device__ float g_K[(size_t)Hh * Ll * Dd];          // 64 MB  [H][L][D]
__device__ float g_V[(size_t)Hh * Ll * Dd];          // 64 MB  [H][L][D]
__device__ float g_S[(size_t)Hh * Mm * Ll];          // 256 MB [H*M][L]  scores -> exp(scores)
__device__ float g_invs[Hh * Mm];                    // 1/sum(exp(s)) per row

// ---------------------------------------------------------------------------
// Copy caches into scratch (rows P..L get overwritten by the QKV epilogue)
// ---------------------------------------------------------------------------
__global__ void copy_caches(const float* __restrict__ cK, const float* __restrict__ cV) {
    size_t n4 = (size_t)Hh * Ll * Dd / 4;
    const float4* a = (const float4*)cK;
    const float4* b = (const float4*)cV;
    float4* dk = (float4*)g_K;
    float4* dv = (float4*)g_V;
    for (size_t i = (size_t)blockIdx.x * blockDim.x + threadIdx.x; i < n4;
         i += (size_t)gridDim.x * blockDim.x) {
        dk[i] = a[i];
        dv[i] = b[i];
    }
}

// ---------------------------------------------------------------------------
// Tiled fp32 GEMM parameters: 128x128 tile, BK=16, 256 threads, 8x8 microtile
// ---------------------------------------------------------------------------
#define BM 128
#define BN 128
#define BK 16
#define TM 8
#define TN 8
#define PADM (BM + 8)   // row stride 136 floats = 544 B (16B aligned)
#define PADN (BN + 8)

// ---------------------------------------------------------------------------
// GEMM 1: QKV projection. z selects W_q / W_k / W_v.
// C[m,n] = sum_k X[m,k] * W[k,n]; epilogue scatters into g_q / g_K / g_V.
// grid (Nn/BN=32, Mm/BM=4, 3)
// ---------------------------------------------------------------------------
__global__ __launch_bounds__(256, 2)
void gemm_qkv(const float* __restrict__ X,
              const float* __restrict__ Wq,
              const float* __restrict__ Wk,
              const float* __restrict__ Wv) {
    const int z = blockIdx.z;
    const float* W = (z == 0) ? Wq : ((z == 1) ? Wk : Wv);
    const int bm0 = blockIdx.y * BM;
    const int bn0 = blockIdx.x * BN;
    __shared__ float As[BK][PADM];
    __shared__ float Bs[BK][PADN];
    const int tid = threadIdx.x;
    const int tx = tid & 15, ty = tid >> 4;

    float acc[TM][TN];
#pragma unroll
    for (int i = 0; i < TM; i++)
#pragma unroll
        for (int j = 0; j < TN; j++) acc[i][j] = 0.f;

    float4 ra[2], rb[2];
    // initial fetch (k0 = 0)
#pragma unroll
    for (int i = 0; i < 2; i++) {
        int idx = tid + i * 256;
        int r = idx >> 2, c4 = (idx & 3) * 4;
        ra[i] = *(const float4*)&X[(size_t)(bm0 + r) * Kdim + c4];
        int br = idx >> 5, bc = (idx & 31) * 4;
        rb[i] = *(const float4*)&W[(size_t)br * Nn + bn0 + bc];
    }

    for (int k0 = 0; k0 < Kdim; k0 += BK) {
#pragma unroll
        for (int i = 0; i < 2; i++) {
            int idx = tid + i * 256;
            int r = idx >> 2, c4 = (idx & 3) * 4;
            As[c4 + 0][r] = ra[i].x; As[c4 + 1][r] = ra[i].y;
            As[c4 + 2][r] = ra[i].z; As[c4 + 3][r] = ra[i].w;
            int br = idx >> 5, bc = (idx & 31) * 4;
            *(float4*)&Bs[br][bc] = rb[i];
        }
        __syncthreads();
        if (k0 + BK < Kdim) {
            int kn = k0 + BK;
#pragma unroll
            for (int i = 0; i < 2; i++) {
                int idx = tid + i * 256;
                int r = idx >> 2, c4 = (idx & 3) * 4;
                ra[i] = *(const float4*)&X[(size_t)(bm0 + r) * Kdim + kn + c4];
                int br = idx >> 5, bc = (idx & 31) * 4;
                rb[i] = *(const float4*)&W[(size_t)(kn + br) * Nn + bn0 + bc];
            }
        }
#pragma unroll
        for (int kk = 0; kk < BK; kk++) {
            float a[TM], b[TN];
#pragma unroll
            for (int i = 0; i < TM; i += 4) *(float4*)&a[i] = *(const float4*)&As[kk][ty * TM + i];
#pragma unroll
            for (int j = 0; j < TN; j += 4) *(float4*)&b[j] = *(const float4*)&Bs[kk][tx * TN + j];
#pragma unroll
            for (int i = 0; i < TM; i++)
#pragma unroll
                for (int j = 0; j < TN; j++) acc[i][j] += a[i] * b[j];
        }
        __syncthreads();
    }

#pragma unroll
    for (int i = 0; i < TM; i++) {
        int cm = bm0 + ty * TM + i;
#pragma unroll
        for (int j = 0; j < TN; j++) {
            int cn = bn0 + tx * TN + j;
            int h = cn >> 7, d = cn & 127;
            float v = acc[i][j];
            if (z == 0)      g_q[((size_t)h * Mm + cm) * Dd + d] = v;
            else if (z == 1) g_K[((size_t)h * Ll + (Pp + cm)) * Dd + d] = v;
            else             g_V[((size_t)h * Ll + (Pp + cm)) * Dd + d] = v;
        }
    }
}

// ---------------------------------------------------------------------------
// GEMM 2: scores.  S[h][m][l] = sum_d q[h][m][d] * K[h][l][d]   (A * B^T)
// grid (Ll/BN=32, Mm/BM=4, Hh=32)
// ---------------------------------------------------------------------------
__global__ __launch_bounds__(256, 2)
void gemm_scores() {
    const int h = blockIdx.z;
    const float* A = g_q + (size_t)h * Mm * Dd;
    const float* B = g_K + (size_t)h * Ll * Dd;
    const int bm0 = blockIdx.y * BM;
    const int bn0 = blockIdx.x * BN;
    __shared__ float As[BK][PADM];
    __shared__ float Bs[BK][PADN];
    const int tid = threadIdx.x;
    const int tx = tid & 15, ty = tid >> 4;

    float acc[TM][TN];
#pragma unroll
    for (int i = 0; i < TM; i++)
#pragma unroll
        for (int j = 0; j < TN; j++) acc[i][j] = 0.f;

    float4 ra[2], rb[2];
#pragma unroll
    for (int i = 0; i < 2; i++) {
        int idx = tid + i * 256;
        int r = idx >> 2, c4 = (idx & 3) * 4;
        ra[i] = *(const float4*)&A[(size_t)(bm0 + r) * Dd + c4];
        rb[i] = *(const float4*)&B[(size_t)(bn0 + r) * Dd + c4];
    }

    for (int k0 = 0; k0 < Dd; k0 += BK) {
#pragma unroll
        for (int i = 0; i < 2; i++) {
            int idx = tid + i * 256;
            int r = idx >> 2, c4 = (idx & 3) * 4;
            As[c4 + 0][r] = ra[i].x; As[c4 + 1][r] = ra[i].y;
            As[c4 + 2][r] = ra[i].z; As[c4 + 3][r] = ra[i].w;
            Bs[c4 + 0][r] = rb[i].x; Bs[c4 + 1][r] = rb[i].y;
            Bs[c4 + 2][r] = rb[i].z; Bs[c4 + 3][r] = rb[i].w;
        }
        __syncthreads();
        if (k0 + BK < Dd) {
            int kn = k0 + BK;
#pragma unroll
            for (int i = 0; i < 2; i++) {
                int idx = tid + i * 256;
                int r = idx >> 2, c4 = (idx & 3) * 4;
                ra[i] = *(const float4*)&A[(size_t)(bm0 + r) * Dd + kn + c4];
                rb[i] = *(const float4*)&B[(size_t)(bn0 + r) * Dd + kn + c4];
            }
        }
#pragma unroll
        for (int kk = 0; kk < BK; kk++) {
            float a[TM], b[TN];
#pragma unroll
            for (int i = 0; i < TM; i += 4) *(float4*)&a[i] = *(const float4*)&As[kk][ty * TM + i];
#pragma unroll
            for (int j = 0; j < TN; j += 4) *(float4*)&b[j] = *(const float4*)&Bs[kk][tx * TN + j];
#pragma unroll
            for (int i = 0; i < TM; i++)
#pragma unroll
                for (int j = 0; j < TN; j++) acc[i][j] += a[i] * b[j];
        }
        __syncthreads();
    }

#pragma unroll
    for (int i = 0; i < TM; i++) {
        int cm = bm0 + ty * TM + i;
#pragma unroll
        for (int j = 0; j < TN; j++) {
            int cn = bn0 + tx * TN + j;
            g_S[((size_t)h * Mm + cm) * Ll + cn] = acc[i][j];
        }
    }
}

// ---------------------------------------------------------------------------
// Dual-exp row kernel: one block per (h,m) row.
//   g_S row  <- exp(s)              (weights numerator, for output GEMM)
//   perturb  <- exp((s+noise)/1.5) / sum   (written normalized)
//   g_invs   <- 1/sum(exp(s))
// No max subtraction — mirrors the reference exactly; |s| <= ~70 is fp32-safe.
// ---------------------------------------------------------------------------
__global__ __launch_bounds__(256)
void softmax_rows(const float* __restrict__ noise, float* __restrict__ dout) {
    const int row = blockIdx.x;  // h*Mm + m
    float* S = g_S + (size_t)row * Ll;
    const float* nz = noise + (size_t)row * Ll;
    float* pout = dout + OUT0 + (size_t)row * Ll;
    __shared__ float ep[Ll];
    __shared__ float r1[256], r2[256];
    const int tid = threadIdx.x;

    float ss = 0.f, sp = 0.f;
    for (int l = tid; l < Ll; l += 256) {
        float s = S[l];
        float es = expf(s);
        S[l] = es;
        ss += es;
        float e2 = expf((s + nz[l]) * (1.0f / 1.5f));
        ep[l] = e2;
        sp += e2;
    }
    r1[tid] = ss; r2[tid] = sp;
    __syncthreads();
    for (int st = 128; st > 0; st >>= 1) {
        if (tid < st) { r1[tid] += r1[tid + st]; r2[tid] += r2[tid + st]; }
        __syncthreads();
    }
    if (tid == 0) g_invs[row] = 1.0f / r1[0];
    const float ip = 1.0f / r2[0];
    for (int l = tid; l < Ll; l += 256) pout[l] = ep[l] * ip;
}

// ---------------------------------------------------------------------------
// GEMM 3: output.  out[h][m][d] = (1/sum_s) * sum_l exp(s)[h][m][l] * V[h][l][d]
// BN = 128 covers the whole head dim.  grid (1, Mm/BM=4, Hh=32)
// Epilogue writes output[m, h*128+d] (head-interleaved layout).
// ---------------------------------------------------------------------------
__global__ __launch_bounds__(256, 2)
void gemm_out(float* __restrict__ dout) {
    const int h = blockIdx.z;
    const float* A = g_S + (size_t)h * Mm * Ll;   // exp(scores), [M][L]
    const float* B = g_V + (size_t)h * Ll * Dd;   // [L][D]
    const int bm0 = blockIdx.y * BM;
    __shared__ float As[BK][PADM];
    __shared__ float Bs[BK][PADN];
    const int tid = threadIdx.x;
    const int tx = tid & 15, ty = tid >> 4;

    float acc[TM][TN];
#pragma unroll
    for (int i = 0; i < TM; i++)
#pragma unroll
        for (int j = 0; j < TN; j++) acc[i][j] = 0.f;

    float4 ra[2], rb[2];
#pragma unroll
    for (int i = 0; i < 2; i++) {
        int idx = tid + i * 256;
        int r = idx >> 2, c4 = (idx & 3) * 4;
        ra[i] = *(const float4*)&A[(size_t)(bm0 + r) * Ll + c4];
        int br = idx >> 5, bc = (idx & 31) * 4;
        rb[i] = *(const float4*)&B[(size_t)br * Dd + bc];
    }

    for (int k0 = 0; k0 < Ll; k0 += BK) {
#pragma unroll
        for (int i = 0; i < 2; i++) {
            int idx = tid + i * 256;
            int r = idx >> 2, c4 = (idx & 3) * 4;
            As[c4 + 0][r] = ra[i].x; As[c4 + 1][r] = ra[i].y;
            As[c4 + 2][r] = ra[i].z; As[c4 + 3][r] = ra[i].w;
            int br = idx >> 5, bc = (idx & 31) * 4;
            *(float4*)&Bs[br][bc] = rb[i];
        }
        __syncthreads();
        if (k0 + BK < Ll) {
            int kn = k0 + BK;
#pragma unroll
            for (int i = 0; i < 2; i++) {
                int idx = tid + i * 256;
                int r = idx >> 2, c4 = (idx & 3) * 4;
                ra[i] = *(const float4*)&A[(size_t)(bm0 + r) * Ll + kn + c4];
                int br = idx >> 5, bc = (idx & 31) * 4;
                rb[i] = *(const float4*)&B[(size_t)(kn + br) * Dd + bc];
            }
        }
#pragma unroll
        for (int kk = 0; kk < BK; kk++) {
            float a[TM], b[TN];
#pragma unroll
            for (int i = 0; i < TM; i += 4) *(float4*)&a[i] = *(const float4*)&As[kk][ty * TM + i];
#pragma unroll
            for (int j = 0; j < TN; j += 4) *(float4*)&b[j] = *(const float4*)&Bs[kk][tx * TN + j];
#pragma unroll
            for (int i = 0; i < TM; i++)
#pragma unroll
                for (int j = 0; j < TN; j++) acc[i][j] += a[i] * b[j];
        }
        __syncthreads();
    }

#pragma unroll
    for (int i = 0; i < TM; i++) {
        int cm = bm0 + ty * TM + i;
        float inv = g_invs[h * Mm + cm];
#pragma unroll
        for (int j = 0; j < TN; j++) {
            int cn = tx * TN + j;  // d in [0,128)
            dout[(size_t)cm * Nn + h * Dd + cn] = acc[i][j] * inv;
        }
    }
}

// ---------------------------------------------------------------------------
// Launch
// ---------------------------------------------------------------------------
extern "C" void kernel_launch(void* const* d_in, const int* in_sizes, int n_in,
                              void* d_out, int out_size) {
    const float* X      = (const float*)d_in[0];
    const float* Wq     = (const float*)d_in[1];
    const float* Wk     = (const float*)d_in[2];
    const float* Wv     = (const float*)d_in[3];
    const float* noise  = (const float*)d_in[4];
    const float* cacheK = (const float*)d_in[5];
    const float* cacheV = (const float*)d_in[6];
    float* out = (float*)d_out;
    (void)in_sizes; (void)n_in; (void)out_size;   // P is static (3584)

    copy_caches<<<8192, 256>>>(cacheK, cacheV);
    gemm_qkv<<<dim3(Nn / BN, Mm / BM, 3), 256>>>(X, Wq, Wk, Wv);
    gemm_scores<<<dim3(Ll / BN, Mm / BM, Hh), 256>>>();
    softmax_rows<<<Hh * Mm, 256>>>(noise, out);
    gemm_out<<<dim3(1, Mm / BM, Hh), 256>>>(out);
}

// round 6
// speedup vs baseline: 1.2994x; 1.2994x over previous
#include <cuda_runtime.h>
#include <cstdint>
#include <cstddef>

// Problem constants (static in reference)
constexpr int Mm = 512, Nn = 4096, Kdim = 4096, Dd = 128, Hh = 32, Ll = 4096, Pp = 3584;
constexpr size_t OUT0 = (size_t)Mm * Nn;

// Scratch (device globals: allocation-free per harness rules)
__device__ float g_q[(size_t)Hh * Mm * Dd];          //  8 MB  [H][M][D]
__device__ float g_K[(size_t)Hh * Ll * Dd];          // 64 MB  [H][L][D]
__device__ float g_V[(size_t)Hh * Ll * Dd];          // 64 MB  [H][L][D]
__device__ float g_S[(size_t)Hh * Mm * Ll];          // 256 MB [H*M][L]  scores -> exp(scores)
__device__ float g_invs[Hh * Mm];                    // 1/sum(exp(s)) per row

// ---------------------------------------------------------------------------
// TF32 helpers (baseline PTX only — no sm_103a-suffixed features)
// ---------------------------------------------------------------------------
__device__ __forceinline__ void tf32split(float f, uint32_t& hi, uint32_t& lo) {
    asm("cvt.rna.tf32.f32 %0, %1;" : "=r"(hi) : "f"(f));
    float r = f - __uint_as_float(hi);
    asm("cvt.rna.tf32.f32 %0, %1;" : "=r"(lo) : "f"(r));
}

// D += A(16x8, row) * B(8x8, col);  C/D f32, A/B tf32
__device__ __forceinline__ void mma8(float* c, const uint32_t* a, const uint32_t* b) {
    asm("mma.sync.aligned.m16n8k8.row.col.f32.tf32.tf32.f32 "
        "{%0,%1,%2,%3}, {%4,%5,%6,%7}, {%8,%9}, {%0,%1,%2,%3};"
        : "+f"(c[0]), "+f"(c[1]), "+f"(c[2]), "+f"(c[3])
        : "r"(a[0]), "r"(a[1]), "r"(a[2]), "r"(a[3]), "r"(b[0]), "r"(b[1]));
}

// ---------------------------------------------------------------------------
// GEMM core: C[128,128] = A[128xK] * B  (B fed as smem [k][n] tiles)
// 256 threads = 8 warps (4M x 2N); warp tile 32x64 = 2x8 m16n8k8 tiles.
// 3xTF32: acc += ah*bh + ah*bl + al*bh.
// SMEM: raw fp32 tiles, double buffered. A stride 20, B stride 132 (pad).
// ---------------------------------------------------------------------------
#define AS_STR 20
#define BS_STR 132

struct F4x2 { float4 a, b; };

__device__ __forceinline__ F4x2 fetchA(const float* __restrict__ A, size_t lda,
                                       int am0, int k0, int tid) {
    int r = tid >> 1, kq = (tid & 1) * 8;
    const float* p = A + (size_t)(am0 + r) * lda + k0 + kq;
    F4x2 v; v.a = *(const float4*)p; v.b = *(const float4*)(p + 4);
    return v;
}
__device__ __forceinline__ F4x2 fetchB_dir(const float* __restrict__ B, size_t ldb,
                                           int bn0, int k0, int tid) {
    int k = tid >> 4, n0 = (tid & 15) * 4;
    const float* p = B + (size_t)(k0 + k) * ldb + bn0 + n0;
    F4x2 v; v.a = *(const float4*)p; v.b = *(const float4*)(p + 64);
    return v;
}
__device__ __forceinline__ F4x2 fetchB_trn(const float* __restrict__ B, size_t ldb,
                                           int bn0, int k0, int tid) {
    int l = tid >> 1, dq = (tid & 1) * 8;
    const float* p = B + (size_t)(bn0 + l) * ldb + k0 + dq;
    F4x2 v; v.a = *(const float4*)p; v.b = *(const float4*)(p + 4);
    return v;
}

__device__ __forceinline__ void stA(float* As, F4x2 v, int tid) {
    int r = tid >> 1, kq = (tid & 1) * 8;
    *(float4*)&As[r * AS_STR + kq]     = v.a;
    *(float4*)&As[r * AS_STR + kq + 4] = v.b;
}
__device__ __forceinline__ void stB_dir(float* Bs, F4x2 v, int tid) {
    int k = tid >> 4, n0 = (tid & 15) * 4;
    *(float4*)&Bs[k * BS_STR + n0]      = v.a;
    *(float4*)&Bs[k * BS_STR + n0 + 64] = v.b;
}
__device__ __forceinline__ void stB_trn(float* Bs, F4x2 v, int tid) {
    int l = tid >> 1, dq = (tid & 1) * 8;
    float f0[4] = {v.a.x, v.a.y, v.a.z, v.a.w};
    float f1[4] = {v.b.x, v.b.y, v.b.z, v.b.w};
#pragma unroll
    for (int j = 0; j < 4; j++) {
        Bs[(dq + j) * BS_STR + l]     = f0[j];
        Bs[(dq + 4 + j) * BS_STR + l] = f1[j];
    }
}

template <int NCHUNK, bool BTRANS>
__device__ __forceinline__ void gemm_tc(const float* __restrict__ A, size_t lda, int am0,
                                        const float* __restrict__ B, size_t ldb, int bn0,
                                        float (&sA)[2][128 * AS_STR],
                                        float (&sB)[2][16 * BS_STR],
                                        float (&acc)[2][8][4]) {
    const int tid = threadIdx.x;
    const int lane = tid & 31, wid = tid >> 5;
    const int wm0 = (wid >> 1) * 32, wn0 = (wid & 1) * 64;
    const int g = lane >> 2, t4 = lane & 3;

#pragma unroll
    for (int i = 0; i < 2; i++)
#pragma unroll
        for (int j = 0; j < 8; j++)
#pragma unroll
            for (int q = 0; q < 4; q++) acc[i][j][q] = 0.f;

    F4x2 ra = fetchA(A, lda, am0, 0, tid);
    F4x2 rb = BTRANS ? fetchB_trn(B, ldb, bn0, 0, tid)
                     : fetchB_dir(B, ldb, bn0, 0, tid);

#pragma unroll 1
    for (int c = 0; c < NCHUNK; c++) {
        float* As = sA[c & 1];
        float* Bs = sB[c & 1];
        stA(As, ra, tid);
        if (BTRANS) stB_trn(Bs, rb, tid); else stB_dir(Bs, rb, tid);
        __syncthreads();
        if (c + 1 < NCHUNK) {
            ra = fetchA(A, lda, am0, (c + 1) * 16, tid);
            rb = BTRANS ? fetchB_trn(B, ldb, bn0, (c + 1) * 16, tid)
                        : fetchB_dir(B, ldb, bn0, (c + 1) * 16, tid);
        }
#pragma unroll
        for (int kt = 0; kt < 2; kt++) {
            uint32_t ah[2][4], al[2][4], bh[8][2], bl[8][2];
#pragma unroll
            for (int i = 0; i < 2; i++) {
                int mr = wm0 + i * 16 + g;
                int kc = kt * 8 + t4;
                float x0 = As[mr * AS_STR + kc];
                float x1 = As[(mr + 8) * AS_STR + kc];
                float x2 = As[mr * AS_STR + kc + 4];
                float x3 = As[(mr + 8) * AS_STR + kc + 4];
                tf32split(x0, ah[i][0], al[i][0]);
                tf32split(x1, ah[i][1], al[i][1]);
                tf32split(x2, ah[i][2], al[i][2]);
                tf32split(x3, ah[i][3], al[i][3]);
            }
#pragma unroll
            for (int j = 0; j < 8; j++) {
                int n = wn0 + j * 8 + g;
                int kc = kt * 8 + t4;
                float y0 = Bs[kc * BS_STR + n];
                float y1 = Bs[(kc + 4) * BS_STR + n];
                tf32split(y0, bh[j][0], bl[j][0]);
                tf32split(y1, bh[j][1], bl[j][1]);
            }
#pragma unroll
            for (int i = 0; i < 2; i++)
#pragma unroll
                for (int j = 0; j < 8; j++) {
                    mma8(acc[i][j], ah[i], bh[j]);
                    mma8(acc[i][j], ah[i], bl[j]);
                    mma8(acc[i][j], al[i], bh[j]);
                }
        }
        __syncthreads();
    }
}

__device__ __forceinline__ void store_acc(float (&acc)[2][8][4], float* __restrict__ dst,
                                          size_t ldd, const float* __restrict__ rowscale) {
    const int tid = threadIdx.x;
    const int lane = tid & 31, wid = tid >> 5;
    const int wm0 = (wid >> 1) * 32, wn0 = (wid & 1) * 64;
    const int g = lane >> 2, t4 = lane & 3;
#pragma unroll
    for (int i = 0; i < 2; i++) {
        int r0 = wm0 + i * 16 + g;
        float s0 = rowscale ? rowscale[r0] : 1.f;
        float s1 = rowscale ? rowscale[r0 + 8] : 1.f;
#pragma unroll
        for (int j = 0; j < 8; j++) {
            int cn = wn0 + j * 8 + t4 * 2;
            float2 v0 = make_float2(acc[i][j][0] * s0, acc[i][j][1] * s0);
            float2 v1 = make_float2(acc[i][j][2] * s1, acc[i][j][3] * s1);
            *(float2*)&dst[(size_t)r0 * ldd + cn] = v0;
            *(float2*)&dst[(size_t)(r0 + 8) * ldd + cn] = v1;
        }
    }
}

// ---------------------------------------------------------------------------
// Kernels
// ---------------------------------------------------------------------------

// QKV: C = X @ W_z, one (m-block, z, head) tile per CTA; scatter to q / caches
__global__ __launch_bounds__(256)
void k_qkv(const float* __restrict__ X, const float* __restrict__ Wq,
           const float* __restrict__ Wk, const float* __restrict__ Wv) {
    __shared__ float sA[2][128 * AS_STR];
    __shared__ float sB[2][16 * BS_STR];
    int z = blockIdx.x >> 5, head = blockIdx.x & 31;
    const float* W = (z == 0) ? Wq : (z == 1) ? Wk : Wv;
    int bm0 = blockIdx.y * 128;
    float acc[2][8][4];
    gemm_tc<Kdim / 16, false>(X, Kdim, bm0, W, Nn, head * 128, sA, sB, acc);
    float* dst = (z == 0) ? g_q + ((size_t)head * Mm + bm0) * Dd
               : (z == 1) ? g_K + ((size_t)head * Ll + Pp + bm0) * Dd
                          : g_V + ((size_t)head * Ll + Pp + bm0) * Dd;
    store_acc(acc, dst, Dd, nullptr);
}

// Scores: S[h][m][l] = q[h] @ K[h]^T  (K-cache transposed on smem store)
__global__ __launch_bounds__(256)
void k_scores() {
    __shared__ float sA[2][128 * AS_STR];
    __shared__ float sB[2][16 * BS_STR];
    int h = blockIdx.z, bm0 = blockIdx.y * 128, l0 = blockIdx.x * 128;
    float acc[2][8][4];
    gemm_tc<Dd / 16, true>(g_q + (size_t)h * Mm * Dd, Dd, bm0,
                           g_K + (size_t)h * Ll * Dd, Dd, l0, sA, sB, acc);
    store_acc(acc, g_S + ((size_t)h * Mm + bm0) * Ll + l0, Ll, nullptr);
}

// Output: out[m, h*128+d] = (exp(S)[h] @ V[h]) * inv_sum
__global__ __launch_bounds__(256)
void k_out(float* __restrict__ dout) {
    __shared__ float sA[2][128 * AS_STR];
    __shared__ float sB[2][16 * BS_STR];
    int h = blockIdx.y, bm0 = blockIdx.x * 128;
    float acc[2][8][4];
    gemm_tc<Ll / 16, false>(g_S + (size_t)h * Mm * Ll, Ll, bm0,
                            g_V + (size_t)h * Ll * Dd, Dd, 0, sA, sB, acc);
    store_acc(acc, dout + (size_t)bm0 * Nn + h * Dd, Nn, g_invs + h * Mm + bm0);
}

// Copy only cache rows [0, P) — rows [P, L) are overwritten by the QKV epilogue.
__global__ void copy_caches(const float* __restrict__ cK, const float* __restrict__ cV) {
    constexpr size_t PER_HEAD = (size_t)Pp * Dd / 4;
    constexpr size_t FULL_HEAD = (size_t)Ll * Dd / 4;
    size_t n4 = (size_t)Hh * PER_HEAD;
    for (size_t i = (size_t)blockIdx.x * blockDim.x + threadIdx.x; i < n4;
         i += (size_t)gridDim.x * blockDim.x) {
        size_t h = i / PER_HEAD, r = i - h * PER_HEAD;
        size_t off = h * FULL_HEAD + r;
        ((float4*)g_K)[off] = ((const float4*)cK)[off];
        ((float4*)g_V)[off] = ((const float4*)cV)[off];
    }
}

// Dual-exp row kernel: g_S <- exp(s), perturb normalized, g_invs = 1/sum(exp).
__global__ __launch_bounds__(256)
void softmax_rows(const float* __restrict__ noise, float* __restrict__ dout) {
    const int row = blockIdx.x;  // h*Mm + m
    float* S = g_S + (size_t)row * Ll;
    const float* nz = noise + (size_t)row * Ll;
    float* pout = dout + OUT0 + (size_t)row * Ll;
    __shared__ float ep[Ll];
    __shared__ float r1[256], r2[256];
    const int tid = threadIdx.x;

    float ss = 0.f, sp = 0.f;
    for (int l = tid; l < Ll; l += 256) {
        float s = S[l];
        float es = expf(s);
        S[l] = es;
        ss += es;
        float e2 = expf((s + nz[l]) * (1.0f / 1.5f));
        ep[l] = e2;
        sp += e2;
    }
    r1[tid] = ss; r2[tid] = sp;
    __syncthreads();
    for (int st = 128; st > 0; st >>= 1) {
        if (tid < st) { r1[tid] += r1[tid + st]; r2[tid] += r2[tid + st]; }
        __syncthreads();
    }
    if (tid == 0) g_invs[row] = 1.0f / r1[0];
    const float ip = 1.0f / r2[0];
    for (int l = tid; l < Ll; l += 256) pout[l] = ep[l] * ip;
}

// ---------------------------------------------------------------------------
// Launch
// ---------------------------------------------------------------------------
extern "C" void kernel_launch(void* const* d_in, const int* in_sizes, int n_in,
                              void* d_out, int out_size) {
    const float* X      = (const float*)d_in[0];
    const float* Wq     = (const float*)d_in[1];
    const float* Wk     = (const float*)d_in[2];
    const float* Wv     = (const float*)d_in[3];
    const float* noise  = (const float*)d_in[4];
    const float* cacheK = (const float*)d_in[5];
    const float* cacheV = (const float*)d_in[6];
    float* out = (float*)d_out;
    (void)in_sizes; (void)n_in; (void)out_size;   // P is static (3584)

    copy_caches<<<2048, 256>>>(cacheK, cacheV);
    k_qkv<<<dim3(96, 4), 256>>>(X, Wq, Wk, Wv);
    k_scores<<<dim3(32, 4, 32), 256>>>();
    softmax_rows<<<Hh * Mm, 256>>>(noise, out);
    k_out<<<dim3(4, 32), 256>>>(out);
}